// round 7
// baseline (speedup 1.0000x reference)
#include <cuda_runtime.h>

#ifndef EPSF
#define EPSF 1e-07f
#endif

#define NTHREADS 256
#define TILE     1024              // boxes per tile (16 KB per array)
#define MAXBLK   8192

static __device__ float        g_partials[MAXBLK];
static __device__ unsigned int g_count;   // zero at load; atomicInc wrap self-resets

__device__ __forceinline__ void prefetch_l2(const void* p, unsigned bytes) {
    asm volatile("cp.async.bulk.prefetch.L2.global [%0], %1;"
                 :: "l"(p), "r"(bytes) : "memory");
}

__device__ __forceinline__ float ciou_term(float4 p, float4 t) {
    float px1 = p.x, py1 = p.y, px2 = p.z, py2 = p.w;
    float tx1 = t.x, ty1 = t.y, tx2 = t.z, ty2 = t.w;

    float iw = fmaxf(fminf(px2, tx2) - fmaxf(px1, tx1), 0.0f);
    float ih = fmaxf(fminf(py2, ty2) - fmaxf(py1, ty1), 0.0f);
    float inter = iw * ih;

    float pw = px2 - px1, ph = py2 - py1;
    float tw = tx2 - tx1, th = ty2 - ty1;

    float d_iou = pw * ph + tw * th - inter + EPSF;   // union area + eps

    float dcx = 0.5f * (px1 + px2) - 0.5f * (tx1 + tx2);
    float dcy = 0.5f * (py1 + py2) - 0.5f * (ty1 + ty2);
    float center_dist_sq = dcx * dcx + dcy * dcy;

    float cw = fmaxf(px2, tx2) - fminf(px1, tx1);
    float ch = fmaxf(py2, ty2) - fminf(py1, ty1);
    float c_diag_sq = cw * cw + ch * ch + EPSF;       // eps inside bbox_iou
    float d_ctr = c_diag_sq + EPSF;                   // eps again in forward()

    // one reciprocal serves two divides
    float inv12 = __fdividef(1.0f, d_iou * d_ctr);
    float iou         = inter * d_ctr * inv12;
    float center_term = center_dist_sq * d_iou * inv12;

    float d3 = tw + EPSF, d4 = th + EPSF;
    float inv34 = __fdividef(1.0f, d3 * d4);
    float sw = (pw - tw) * d4 * inv34;
    float sh = (ph - th) * d3 * inv34;

    return (1.0f - iou) + 2.0f * center_term + (sw * sw + sh * sh);
}

__global__ void __launch_bounds__(NTHREADS, 6)
ciou_fused_kernel(const float4* __restrict__ pred,
                  const float4* __restrict__ targ,
                  float* __restrict__ out,
                  int n) {
    const int ntiles = (n + TILE - 1) / TILE;
    float local = 0.0f;

    for (int t = blockIdx.x; t < ntiles; t += gridDim.x) {
        // prefetch this CTA's NEXT tile into L2 while we chew on this one
        int tn = t + gridDim.x;
        if (threadIdx.x == 0 && tn < ntiles) {
            long base = (long)tn * TILE;
            prefetch_l2(&pred[base], TILE * 16u);
            prefetch_l2(&targ[base], TILE * 16u);
        }

        int tile_base = t * TILE;
        if (tile_base + TILE <= n) {
            #pragma unroll
            for (int k = 0; k < TILE / NTHREADS; k++) {
                int i = tile_base + k * NTHREADS + threadIdx.x;
                local += ciou_term(pred[i], targ[i]);
            }
        } else {
            for (int k = 0; k < TILE / NTHREADS; k++) {
                int i = tile_base + k * NTHREADS + threadIdx.x;
                if (i < n) local += ciou_term(pred[i], targ[i]);
            }
        }
    }

    // intra-block reduce
    #pragma unroll
    for (int off = 16; off > 0; off >>= 1)
        local += __shfl_down_sync(0xFFFFFFFFu, local, off);

    __shared__ float warp_sums[NTHREADS / 32];
    int lane = threadIdx.x & 31;
    int wid  = threadIdx.x >> 5;
    if (lane == 0) warp_sums[wid] = local;
    __syncthreads();

    __shared__ bool amLast;
    if (threadIdx.x == 0) {
        float bsum = 0.0f;
        #pragma unroll
        for (int w = 0; w < NTHREADS / 32; w++) bsum += warp_sums[w];
        g_partials[blockIdx.x] = bsum;
        __threadfence();
        unsigned int pos = atomicInc(&g_count, gridDim.x - 1);
        amLast = (pos == gridDim.x - 1);
    }
    __syncthreads();

    if (amLast) {
        double v = 0.0;
        for (int j = threadIdx.x; j < gridDim.x; j += NTHREADS)
            v += (double)g_partials[j];
        #pragma unroll
        for (int off = 16; off > 0; off >>= 1)
            v += __shfl_down_sync(0xFFFFFFFFu, v, off);

        __shared__ double dsums[NTHREADS / 32];
        if (lane == 0) dsums[wid] = v;
        __syncthreads();
        if (threadIdx.x == 0) {
            double tot = 0.0;
            #pragma unroll
            for (int w = 0; w < NTHREADS / 32; w++) tot += dsums[w];
            out[0] = (float)(tot / (double)n);
        }
    }
}

extern "C" void kernel_launch(void* const* d_in, const int* in_sizes, int n_in,
                              void* d_out, int out_size) {
    const float4* pred = (const float4*)d_in[0];
    const float4* targ = (const float4*)d_in[1];
    int n = in_sizes[0] / 4;   // floats -> boxes

    int ntiles = (n + TILE - 1) / TILE;
    int blocks = 148 * 6;              // 888: 6 CTAs/SM, grid-stride over tiles
    if (blocks > ntiles) blocks = ntiles;
    if (blocks > MAXBLK) blocks = MAXBLK;
    if (blocks < 1) blocks = 1;

    ciou_fused_kernel<<<blocks, NTHREADS>>>(pred, targ, (float*)d_out, n);
}

// round 8
// speedup vs baseline: 1.0334x; 1.0334x over previous
#include <cuda_runtime.h>
#include <cstdint>

#define EPSF     1e-07f
#define NTHREADS 256
#define TILE     1024          // boxes per stage per CTA
#define STAGES   3
#define MAXGRID  1024

static __device__ float        g_partials[MAXGRID];
static __device__ unsigned int g_count;   // zero at load; atomicInc wrap self-resets

// ---------- PTX helpers ----------
__device__ __forceinline__ uint32_t smem_u32(const void* p) {
    return (uint32_t)__cvta_generic_to_shared(p);
}
__device__ __forceinline__ void mbar_init(uint32_t a, uint32_t cnt) {
    asm volatile("mbarrier.init.shared.b64 [%0], %1;" :: "r"(a), "r"(cnt) : "memory");
}
__device__ __forceinline__ void mbar_expect_tx(uint32_t a, uint32_t bytes) {
    asm volatile("mbarrier.arrive.expect_tx.shared.b64 _, [%0], %1;"
                 :: "r"(a), "r"(bytes) : "memory");
}
__device__ __forceinline__ void mbar_wait(uint32_t a, uint32_t parity) {
    asm volatile(
        "{\n\t.reg .pred P;\n\t"
        "WL_%=:\n\t"
        "mbarrier.try_wait.parity.acquire.cta.shared::cta.b64 P, [%0], %1, 0x989680;\n\t"
        "@P bra.uni WD_%=;\n\t"
        "bra.uni WL_%=;\n\t"
        "WD_%=:\n\t}"
        :: "r"(a), "r"(parity) : "memory");
}
__device__ __forceinline__ void bulk_g2s(uint32_t dst, const void* src,
                                         uint32_t bytes, uint32_t mbar) {
    asm volatile(
        "cp.async.bulk.shared::cta.global.mbarrier::complete_tx::bytes [%0], [%1], %2, [%3];"
        :: "r"(dst), "l"(src), "r"(bytes), "r"(mbar) : "memory");
}
__device__ __forceinline__ void fence_proxy_async_s() {
    asm volatile("fence.proxy.async.shared::cta;" ::: "memory");
}

// ---------- math ----------
__device__ __forceinline__ float ciou_term(float4 p, float4 t) {
    float px1 = p.x, py1 = p.y, px2 = p.z, py2 = p.w;
    float tx1 = t.x, ty1 = t.y, tx2 = t.z, ty2 = t.w;

    float iw = fmaxf(fminf(px2, tx2) - fmaxf(px1, tx1), 0.0f);
    float ih = fmaxf(fminf(py2, ty2) - fmaxf(py1, ty1), 0.0f);
    float inter = iw * ih;

    float pw = px2 - px1, ph = py2 - py1;
    float tw = tx2 - tx1, th = ty2 - ty1;

    float d_iou = pw * ph + tw * th - inter + EPSF;   // union + eps

    float dcx = 0.5f * (px1 + px2) - 0.5f * (tx1 + tx2);
    float dcy = 0.5f * (py1 + py2) - 0.5f * (ty1 + ty2);
    float center_dist_sq = dcx * dcx + dcy * dcy;

    float cw = fmaxf(px2, tx2) - fminf(px1, tx1);
    float ch = fmaxf(py2, ty2) - fminf(py1, ty1);
    float c_diag_sq = cw * cw + ch * ch + EPSF;       // eps inside bbox_iou
    float d_ctr = c_diag_sq + EPSF;                   // eps again in forward()

    float inv12 = __fdividef(1.0f, d_iou * d_ctr);    // one rcp, two divides
    float iou         = inter * d_ctr * inv12;
    float center_term = center_dist_sq * d_iou * inv12;

    float d3 = tw + EPSF, d4 = th + EPSF;
    float inv34 = __fdividef(1.0f, d3 * d4);
    float sw = (pw - tw) * d4 * inv34;
    float sh = (ph - th) * d3 * inv34;

    return (1.0f - iou) + 2.0f * center_term + (sw * sw + sh * sh);
}

extern __shared__ __align__(128) unsigned char smem_raw[];

__global__ void __launch_bounds__(NTHREADS, 2)
ciou_tma_kernel(const float4* __restrict__ pred,
                const float4* __restrict__ targ,
                float* __restrict__ out, int n) {
    const int tid    = threadIdx.x;
    const int G      = gridDim.x;
    const int ntiles = n / TILE;

    uint64_t* mbar  = (uint64_t*)smem_raw;                 // STAGES barriers
    float4*   tiles = (float4*)(smem_raw + 128);           // stage s: [pred TILE][targ TILE]

    if (tid == 0) {
        #pragma unroll
        for (int s = 0; s < STAGES; s++) mbar_init(smem_u32(&mbar[s]), 1);
        fence_proxy_async_s();
    }
    __syncthreads();

    float local = 0.0f;

    // remainder boxes (n not multiple of TILE) -> block 0, plain LDG
    if (blockIdx.x == 0) {
        for (int i = ntiles * TILE + tid; i < n; i += NTHREADS)
            local += ciou_term(pred[i], targ[i]);
    }

    // tiles for this CTA: blockIdx.x, +G, +2G, ...
    int myTiles = (ntiles > (int)blockIdx.x) ? ((ntiles - 1 - blockIdx.x) / G + 1) : 0;

    // prologue: fill pipeline
    if (tid == 0) {
        for (int j = 0; j < STAGES && j < myTiles; j++) {
            long t = (long)blockIdx.x + (long)j * G;
            uint32_t mb = smem_u32(&mbar[j]);
            uint32_t ds = smem_u32(tiles + (size_t)j * 2 * TILE);
            mbar_expect_tx(mb, TILE * 32u);
            bulk_g2s(ds,              pred + t * TILE, TILE * 16u, mb);
            bulk_g2s(ds + TILE * 16u, targ + t * TILE, TILE * 16u, mb);
        }
    }
    int issued = (myTiles < STAGES) ? myTiles : STAGES;

    for (int j = 0; j < myTiles; j++) {
        int s = j % STAGES;
        mbar_wait(smem_u32(&mbar[s]), (unsigned)((j / STAGES) & 1));

        const float4* sp = tiles + (size_t)s * 2 * TILE;
        const float4* st = sp + TILE;
        #pragma unroll
        for (int k = 0; k < TILE / NTHREADS; k++)
            local += ciou_term(sp[k * NTHREADS + tid], st[k * NTHREADS + tid]);

        __syncthreads();   // all readers done with stage s before refill
        if (tid == 0 && issued < myTiles) {
            long t = (long)blockIdx.x + (long)issued * G;   // issued % STAGES == s
            uint32_t mb = smem_u32(&mbar[s]);
            uint32_t ds = smem_u32(tiles + (size_t)s * 2 * TILE);
            mbar_expect_tx(mb, TILE * 32u);
            bulk_g2s(ds,              pred + t * TILE, TILE * 16u, mb);
            bulk_g2s(ds + TILE * 16u, targ + t * TILE, TILE * 16u, mb);
        }
        issued++;
    }

    // ---------- reduction ----------
    #pragma unroll
    for (int off = 16; off > 0; off >>= 1)
        local += __shfl_down_sync(0xFFFFFFFFu, local, off);

    __shared__ float warp_sums[NTHREADS / 32];
    int lane = threadIdx.x & 31;
    int wid  = threadIdx.x >> 5;
    if (lane == 0) warp_sums[wid] = local;
    __syncthreads();

    __shared__ bool amLast;
    if (tid == 0) {
        float bsum = 0.0f;
        #pragma unroll
        for (int w = 0; w < NTHREADS / 32; w++) bsum += warp_sums[w];
        g_partials[blockIdx.x] = bsum;
        __threadfence();
        unsigned int pos = atomicInc(&g_count, gridDim.x - 1);
        amLast = (pos == gridDim.x - 1);
    }
    __syncthreads();

    if (amLast) {
        double v = 0.0;
        for (int j = tid; j < (int)gridDim.x; j += NTHREADS)
            v += (double)g_partials[j];
        #pragma unroll
        for (int off = 16; off > 0; off >>= 1)
            v += __shfl_down_sync(0xFFFFFFFFu, v, off);

        __shared__ double dsums[NTHREADS / 32];
        if (lane == 0) dsums[wid] = v;
        __syncthreads();
        if (tid == 0) {
            double tot = 0.0;
            #pragma unroll
            for (int w = 0; w < NTHREADS / 32; w++) tot += dsums[w];
            out[0] = (float)(tot / (double)n);
        }
    }
}

extern "C" void kernel_launch(void* const* d_in, const int* in_sizes, int n_in,
                              void* d_out, int out_size) {
    const float4* pred = (const float4*)d_in[0];
    const float4* targ = (const float4*)d_in[1];
    int n = in_sizes[0] / 4;   // floats -> boxes

    int ntiles = n / TILE;
    int G = 296;                       // 2 CTAs/SM on 148 SMs
    if (G > ntiles) G = ntiles;
    if (G < 1) G = 1;
    if (G > MAXGRID) G = MAXGRID;

    size_t smem = 128 + (size_t)STAGES * TILE * 32;   // 96.1 KB
    // persistent per-function attribute; idempotent, safe pre-capture and during
    cudaFuncSetAttribute(ciou_tma_kernel,
                         cudaFuncAttributeMaxDynamicSharedMemorySize, (int)smem);

    ciou_tma_kernel<<<G, NTHREADS, smem>>>(pred, targ, (float*)d_out, n);
}